// round 1
// baseline (speedup 1.0000x reference)
#include <cuda_runtime.h>
#include <cuda_bf16.h>

#define B_ 128
#define L_ 1024
#define V_ 30000
#define D_ 256
#define T_ 64

// Scratch (static device globals: allowed; no allocations anywhere)
__device__ float g_P[V_ * T_];      // projected vocab table: embed @ W + b   (7.68 MB)
__device__ float g_logz[B_];
__device__ float g_score[B_];

// ---------------------------------------------------------------------------
// Kernel 1: P[v][j] = sum_d embed[v][d] * W[d][j] + b[j]
// Block: 256 threads = 16 vocab rows x 16 float4 column-groups.
// Warp reads: embed via broadcast LDG.128, W via coalesced LDG.128 (L1-resident).
// ---------------------------------------------------------------------------
__global__ void __launch_bounds__(256) proj_kernel(const float* __restrict__ embed,
                                                   const float* __restrict__ W,
                                                   const float* __restrict__ bias) {
    int tid  = threadIdx.x;
    int j4   = tid & 15;        // column group: columns j4*4 .. j4*4+3
    int vloc = tid >> 4;
    int v    = blockIdx.x * 16 + vloc;
    if (v >= V_) return;

    const float4* Wv = reinterpret_cast<const float4*>(W);                    // [D_][16]
    const float4* Ev = reinterpret_cast<const float4*>(embed + (size_t)v * D_);
    float4 bb = reinterpret_cast<const float4*>(bias)[j4];
    float ax = bb.x, ay = bb.y, az = bb.z, aw = bb.w;

    #pragma unroll 4
    for (int d4 = 0; d4 < D_ / 4; d4++) {
        float4 e4 = Ev[d4];
        float4 w0 = Wv[(d4 * 4 + 0) * 16 + j4];
        float4 w1 = Wv[(d4 * 4 + 1) * 16 + j4];
        float4 w2 = Wv[(d4 * 4 + 2) * 16 + j4];
        float4 w3 = Wv[(d4 * 4 + 3) * 16 + j4];
        ax = fmaf(e4.x, w0.x, ax); ay = fmaf(e4.x, w0.y, ay);
        az = fmaf(e4.x, w0.z, az); aw = fmaf(e4.x, w0.w, aw);
        ax = fmaf(e4.y, w1.x, ax); ay = fmaf(e4.y, w1.y, ay);
        az = fmaf(e4.y, w1.z, az); aw = fmaf(e4.y, w1.w, aw);
        ax = fmaf(e4.z, w2.x, ax); ay = fmaf(e4.z, w2.y, ay);
        az = fmaf(e4.z, w2.z, az); aw = fmaf(e4.z, w2.w, aw);
        ax = fmaf(e4.w, w3.x, ax); ay = fmaf(e4.w, w3.y, ay);
        az = fmaf(e4.w, w3.z, az); aw = fmaf(e4.w, w3.w, aw);
    }
    float4 out; out.x = ax; out.y = ay; out.z = az; out.w = aw;
    reinterpret_cast<float4*>(g_P)[(size_t)v * 16 + j4] = out;
}

// ---------------------------------------------------------------------------
// Kernel 2: per-row CRF forward (linear semiring + periodic rescale) and gold
// path score. One block per batch row, 128 threads.
// Thread (j = tid&63, h = tid>>6) holds Ereg[i] = exp(trans[h*32+i][j]) in regs.
// ---------------------------------------------------------------------------
__global__ void __launch_bounds__(128) crf_kernel(const int* __restrict__ x,
                                                  const int* __restrict__ tags,
                                                  const float* __restrict__ trans) {
    int row = blockIdx.x;
    int tid = threadIdx.x;
    int j   = tid & 63;
    int h   = tid >> 6;
    bool lo = (tid < 64);

    __shared__ int   stoks[L_];
    __shared__ float p[2][T_];
    __shared__ float part[2][T_];
    __shared__ float red[4];
    __shared__ float s_logscale;

    const int* xrow = x + (size_t)row * L_;
    const int* trow = tags + (size_t)row * L_;

    for (int i = tid; i < L_; i += 128) stoks[i] = xrow[i];
    if (tid == 0) s_logscale = 0.f;

    // exp(transitions) column slice in registers (constant over all steps)
    float E[32];
    #pragma unroll
    for (int i = 0; i < 32; i++)
        E[i] = __expf(trans[(h * 32 + i) * T_ + j]);
    __syncthreads();

    // ---- gold path score ----
    float sc = 0.f;
    for (int pos = tid; pos < L_; pos += 128) {
        int tg = trow[pos];
        sc += g_P[(size_t)stoks[pos] * T_ + tg];
        if (pos + 1 < L_) sc += trans[tg * T_ + trow[pos + 1]];
    }
    #pragma unroll
    for (int o = 16; o; o >>= 1) sc += __shfl_down_sync(0xffffffffu, sc, o);
    if ((tid & 31) == 0) red[tid >> 5] = sc;
    __syncthreads();
    if (tid == 0) {
        float tot = red[0] + red[1] + red[2] + red[3];
        tot += trans[0 * T_ + trow[0]];       // START(0) -> tag0
        tot += trans[trow[L_ - 1] * T_ + 1];  // tag_last -> END(1)
        g_score[row] = tot;
    }
    __syncthreads();

    // ---- forward recursion ----
    float ecur = 0.f, enext = 0.f;
    if (lo) {
        float e0 = g_P[(size_t)stoks[0] * T_ + j];
        p[0][j] = __expf(trans[0 * T_ + j] + e0);   // exp(alpha0); -1e4 -> exact 0
        ecur = g_P[(size_t)stoks[1] * T_ + j];
    }
    __syncthreads();

    for (int t = 1; t < L_; t++) {
        if (lo && t + 1 < L_)
            enext = g_P[(size_t)stoks[t + 1] * T_ + j];   // prefetch next emission row

        int cur = (t - 1) & 1, nxt = t & 1;
        const float* pc = p[cur];
        float s = 0.f;
        #pragma unroll
        for (int i = 0; i < 32; i++)
            s = fmaf(pc[h * 32 + i], E[i], s);
        part[h][j] = s;
        __syncthreads();

        if (lo) {
            float q = (part[0][j] + part[1][j]) * __expf(ecur);
            p[nxt][j] = q;
        }
        __syncthreads();

        if ((t & 7) == 7) {              // rescale: keep magnitudes in fp32 range
            if (lo) {
                float v = p[nxt][j];
                #pragma unroll
                for (int o = 16; o; o >>= 1)
                    v = fmaxf(v, __shfl_down_sync(0xffffffffu, v, o));
                if ((tid & 31) == 0) red[tid >> 5] = v;
            }
            __syncthreads();
            float m = fmaxf(red[0], red[1]);
            float r = __fdividef(1.f, m);
            if (lo) p[nxt][j] *= r;
            if (tid == 0) s_logscale += __logf(m);
            __syncthreads();
        }
        ecur = enext;
    }

    // ---- log partition: log(sum_j q_j * exp(trans[j][END])) + logscale ----
    if (lo) {
        float v = p[(L_ - 1) & 1][j] * __expf(trans[j * T_ + 1]);
        #pragma unroll
        for (int o = 16; o; o >>= 1) v += __shfl_down_sync(0xffffffffu, v, o);
        if ((tid & 31) == 0) red[tid >> 5] = v;
    }
    __syncthreads();
    if (tid == 0)
        g_logz[row] = __logf(red[0] + red[1]) + s_logscale;
}

// ---------------------------------------------------------------------------
// Kernel 3: out = sum_b (logz - score)   ( == -sum(scores - log_z) )
// ---------------------------------------------------------------------------
__global__ void __launch_bounds__(128) reduce_kernel(float* __restrict__ out) {
    int tid = threadIdx.x;
    __shared__ float r[4];
    float v = g_logz[tid] - g_score[tid];
    #pragma unroll
    for (int o = 16; o; o >>= 1) v += __shfl_down_sync(0xffffffffu, v, o);
    if ((tid & 31) == 0) r[tid >> 5] = v;
    __syncthreads();
    if (tid == 0) out[0] = r[0] + r[1] + r[2] + r[3];
}

// ---------------------------------------------------------------------------
// metadata order: x(int), tags(int), mask(f32, unused), embed(f32), W(f32),
//                 b(f32), trans(f32)  -> out: scalar f32
// ---------------------------------------------------------------------------
extern "C" void kernel_launch(void* const* d_in, const int* in_sizes, int n_in,
                              void* d_out, int out_size) {
    const int*   x     = (const int*)d_in[0];
    const int*   tags  = (const int*)d_in[1];
    const float* embed = (const float*)d_in[3];
    const float* W     = (const float*)d_in[4];
    const float* bias  = (const float*)d_in[5];
    const float* trans = (const float*)d_in[6];
    float* out = (float*)d_out;

    proj_kernel<<<(V_ + 15) / 16, 256>>>(embed, W, bias);
    crf_kernel<<<B_, 128>>>(x, tags, trans);
    reduce_kernel<<<1, 128>>>(out);
}

// round 3
// speedup vs baseline: 1.1919x; 1.1919x over previous
#include <cuda_runtime.h>
#include <cuda_bf16.h>

#define B_ 128
#define L_ 1024
#define V_ 30000
#define D_ 256
#define T_ 64

// Scratch (static device globals: allowed; no allocations anywhere)
__device__ float g_P[V_ * T_];      // projected vocab table: embed @ W + b   (7.68 MB)
__device__ float g_logz[B_];
__device__ float g_score[B_];

// ---------------------------------------------------------------------------
// Kernel 1: P[v][j] = sum_d embed[v][d] * W[d][j] + b[j]
// 256 threads: thread = (r4 = tid>>4 -> 4-row group, j4 = tid&15 -> 4-col group)
// Each thread computes a 4x4 output tile => W traffic per FMA cut 4x vs v1.
// ---------------------------------------------------------------------------
__global__ void __launch_bounds__(256) proj_kernel(const float* __restrict__ embed,
                                                   const float* __restrict__ W,
                                                   const float* __restrict__ bias) {
    int tid = threadIdx.x;
    int j4  = tid & 15;           // columns j4*4 .. j4*4+3
    int r4  = tid >> 4;           // row group (4 rows each)
    int vbase = blockIdx.x * 64 + r4 * 4;

    // clamp row indices for the tail block (loads stay in-bounds; stores guarded)
    int v0 = min(vbase + 0, V_ - 1);
    int v1 = min(vbase + 1, V_ - 1);
    int v2 = min(vbase + 2, V_ - 1);
    int v3 = min(vbase + 3, V_ - 1);

    const float4* Wv = reinterpret_cast<const float4*>(W);   // [D_][16] float4
    const float4* E0 = reinterpret_cast<const float4*>(embed + (size_t)v0 * D_);
    const float4* E1 = reinterpret_cast<const float4*>(embed + (size_t)v1 * D_);
    const float4* E2 = reinterpret_cast<const float4*>(embed + (size_t)v2 * D_);
    const float4* E3 = reinterpret_cast<const float4*>(embed + (size_t)v3 * D_);

    float4 bb = reinterpret_cast<const float4*>(bias)[j4];
    float4 a0 = bb, a1 = bb, a2 = bb, a3 = bb;

    #pragma unroll 2
    for (int d4 = 0; d4 < D_ / 4; d4++) {
        float4 w0 = Wv[(d4 * 4 + 0) * 16 + j4];
        float4 w1 = Wv[(d4 * 4 + 1) * 16 + j4];
        float4 w2 = Wv[(d4 * 4 + 2) * 16 + j4];
        float4 w3 = Wv[(d4 * 4 + 3) * 16 + j4];
        float4 e0 = E0[d4], e1 = E1[d4], e2 = E2[d4], e3 = E3[d4];

        a0.x = fmaf(e0.x, w0.x, a0.x); a0.y = fmaf(e0.x, w0.y, a0.y);
        a0.z = fmaf(e0.x, w0.z, a0.z); a0.w = fmaf(e0.x, w0.w, a0.w);
        a0.x = fmaf(e0.y, w1.x, a0.x); a0.y = fmaf(e0.y, w1.y, a0.y);
        a0.z = fmaf(e0.y, w1.z, a0.z); a0.w = fmaf(e0.y, w1.w, a0.w);
        a0.x = fmaf(e0.z, w2.x, a0.x); a0.y = fmaf(e0.z, w2.y, a0.y);
        a0.z = fmaf(e0.z, w2.z, a0.z); a0.w = fmaf(e0.z, w2.w, a0.w);
        a0.x = fmaf(e0.w, w3.x, a0.x); a0.y = fmaf(e0.w, w3.y, a0.y);
        a0.z = fmaf(e0.w, w3.z, a0.z); a0.w = fmaf(e0.w, w3.w, a0.w);

        a1.x = fmaf(e1.x, w0.x, a1.x); a1.y = fmaf(e1.x, w0.y, a1.y);
        a1.z = fmaf(e1.x, w0.z, a1.z); a1.w = fmaf(e1.x, w0.w, a1.w);
        a1.x = fmaf(e1.y, w1.x, a1.x); a1.y = fmaf(e1.y, w1.y, a1.y);
        a1.z = fmaf(e1.y, w1.z, a1.z); a1.w = fmaf(e1.y, w1.w, a1.w);
        a1.x = fmaf(e1.z, w2.x, a1.x); a1.y = fmaf(e1.z, w2.y, a1.y);
        a1.z = fmaf(e1.z, w2.z, a1.z); a1.w = fmaf(e1.z, w2.w, a1.w);
        a1.x = fmaf(e1.w, w3.x, a1.x); a1.y = fmaf(e1.w, w3.y, a1.y);
        a1.z = fmaf(e1.w, w3.z, a1.z); a1.w = fmaf(e1.w, w3.w, a1.w);

        a2.x = fmaf(e2.x, w0.x, a2.x); a2.y = fmaf(e2.x, w0.y, a2.y);
        a2.z = fmaf(e2.x, w0.z, a2.z); a2.w = fmaf(e2.x, w0.w, a2.w);
        a2.x = fmaf(e2.y, w1.x, a2.x); a2.y = fmaf(e2.y, w1.y, a2.y);
        a2.z = fmaf(e2.y, w1.z, a2.z); a2.w = fmaf(e2.y, w1.w, a2.w);
        a2.x = fmaf(e2.z, w2.x, a2.x); a2.y = fmaf(e2.z, w2.y, a2.y);
        a2.z = fmaf(e2.z, w2.z, a2.z); a2.w = fmaf(e2.z, w2.w, a2.w);
        a2.x = fmaf(e2.w, w3.x, a2.x); a2.y = fmaf(e2.w, w3.y, a2.y);
        a2.z = fmaf(e2.w, w3.z, a2.z); a2.w = fmaf(e2.w, w3.w, a2.w);

        a3.x = fmaf(e3.x, w0.x, a3.x); a3.y = fmaf(e3.x, w0.y, a3.y);
        a3.z = fmaf(e3.x, w0.z, a3.z); a3.w = fmaf(e3.x, w0.w, a3.w);
        a3.x = fmaf(e3.y, w1.x, a3.x); a3.y = fmaf(e3.y, w1.y, a3.y);
        a3.z = fmaf(e3.y, w1.z, a3.z); a3.w = fmaf(e3.y, w1.w, a3.w);
        a3.x = fmaf(e3.z, w2.x, a3.x); a3.y = fmaf(e3.z, w2.y, a3.y);
        a3.z = fmaf(e3.z, w2.z, a3.z); a3.w = fmaf(e3.z, w2.w, a3.w);
        a3.x = fmaf(e3.w, w3.x, a3.x); a3.y = fmaf(e3.w, w3.y, a3.y);
        a3.z = fmaf(e3.w, w3.z, a3.z); a3.w = fmaf(e3.w, w3.w, a3.w);
    }

    float4* Pv = reinterpret_cast<float4*>(g_P);
    if (vbase + 0 < V_) Pv[(size_t)(vbase + 0) * 16 + j4] = a0;
    if (vbase + 1 < V_) Pv[(size_t)(vbase + 1) * 16 + j4] = a1;
    if (vbase + 2 < V_) Pv[(size_t)(vbase + 2) * 16 + j4] = a2;
    if (vbase + 3 < V_) Pv[(size_t)(vbase + 3) * 16 + j4] = a3;
}

// ---------------------------------------------------------------------------
// Kernel 2: per-row CRF forward (linear semiring, rescale every 8 steps).
// One block per batch row, 128 threads.
//   warp w (0..3) owns columns j = w*16 .. w*16+15
//   lane = (h = lane>>4, jl = lane&15); thread accumulates its i-half
//   (i in [h*32, h*32+32)), halves merged with one shfl_xor(16).
// ONE __syncthreads per step (double-buffered alpha).
// ---------------------------------------------------------------------------
__global__ void __launch_bounds__(128) crf_kernel(const int* __restrict__ x,
                                                  const int* __restrict__ tags,
                                                  const float* __restrict__ trans) {
    int row  = blockIdx.x;
    int tid  = threadIdx.x;
    int w    = tid >> 5;
    int lane = tid & 31;
    int h    = lane >> 4;
    int jl   = lane & 15;
    int j    = w * 16 + jl;

    __shared__ int   stoks[L_];
    __shared__ float p[2][T_];
    __shared__ float red[4];
    __shared__ float fin[T_];

    const int* xrow = x + (size_t)row * L_;
    const int* trow = tags + (size_t)row * L_;

    for (int i = tid; i < L_; i += 128) stoks[i] = xrow[i];

    // exp(transitions) column slice in registers: E[idx] = exp(trans[h*32+idx][j])
    float E[32];
    #pragma unroll
    for (int i = 0; i < 32; i++)
        E[i] = __expf(trans[(h * 32 + i) * T_ + j]);
    __syncthreads();

    // ---- gold path score ----
    float sc = 0.f;
    for (int pos = tid; pos < L_; pos += 128) {
        int tg = trow[pos];
        sc += __ldg(&g_P[(size_t)stoks[pos] * T_ + tg]);
        if (pos + 1 < L_) sc += trans[tg * T_ + trow[pos + 1]];
    }
    #pragma unroll
    for (int o = 16; o; o >>= 1) sc += __shfl_down_sync(0xffffffffu, sc, o);
    if (lane == 0) red[w] = sc;
    __syncthreads();
    if (tid == 0) {
        float tot = red[0] + red[1] + red[2] + red[3];
        tot += trans[0 * T_ + trow[0]];       // START(0) -> tag0
        tot += trans[trow[L_ - 1] * T_ + 1];  // tag_last -> END(1)
        g_score[row] = tot;
    }

    // ---- init alpha0 (exp-domain); -1e4 transitions underflow to exact 0 ----
    float e0 = __ldg(&g_P[(size_t)stoks[0] * T_ + j]);
    if (h == 0) p[0][j] = __expf(trans[j] + e0);
    // 2-deep emission prefetch pipeline
    float e1 = __ldg(&g_P[(size_t)stoks[1] * T_ + j]);
    float e2 = __ldg(&g_P[(size_t)stoks[2] * T_ + j]);
    float logscale = 0.f;
    __syncthreads();

    for (int t = 1; t < L_; t++) {
        float en = (t + 2 < L_) ? __ldg(&g_P[(size_t)stoks[t + 2] * T_ + j]) : 0.f;

        const float4* qc = reinterpret_cast<const float4*>(p[(t - 1) & 1]) + h * 8;
        float4 vv[8];
        #pragma unroll
        for (int k = 0; k < 8; k++) vv[k] = qc[k];

        float r = 1.f;
        if ((t & 7) == 0) {   // rescale: max of OLD q, folded into this step
            float m = fmaxf(fmaxf(vv[0].x, vv[0].y), fmaxf(vv[0].z, vv[0].w));
            #pragma unroll
            for (int k = 1; k < 8; k++)
                m = fmaxf(m, fmaxf(fmaxf(vv[k].x, vv[k].y), fmaxf(vv[k].z, vv[k].w)));
            m = fmaxf(m, __shfl_xor_sync(0xffffffffu, m, 16));
            r = __fdividef(1.f, m);
            logscale += __logf(m);
        }

        float a0 = 0.f, a1 = 0.f, a2 = 0.f, a3 = 0.f;
        #pragma unroll
        for (int k = 0; k < 8; k++) {
            a0 = fmaf(vv[k].x, E[4 * k + 0], a0);
            a1 = fmaf(vv[k].y, E[4 * k + 1], a1);
            a2 = fmaf(vv[k].z, E[4 * k + 2], a2);
            a3 = fmaf(vv[k].w, E[4 * k + 3], a3);
        }
        float s = (a0 + a1) + (a2 + a3);
        s += __shfl_xor_sync(0xffffffffu, s, 16);   // merge i-halves

        float q = s * (r * __expf(e1));
        if (h == 0) p[t & 1][j] = q;

        e1 = e2; e2 = en;
        __syncthreads();
    }

    // ---- log partition ----
    float v = p[(L_ - 1) & 1][j] * __expf(trans[j * T_ + 1]);
    if (h == 0) fin[j] = v;
    __syncthreads();
    if (tid < 32) {
        float s2 = fin[tid] + fin[tid + 32];
        #pragma unroll
        for (int o = 16; o; o >>= 1) s2 += __shfl_down_sync(0xffffffffu, s2, o);
        if (tid == 0) g_logz[row] = __logf(s2) + logscale;
    }
}

// ---------------------------------------------------------------------------
// Kernel 3: out = sum_b (logz - score)
// ---------------------------------------------------------------------------
__global__ void __launch_bounds__(128) reduce_kernel(float* __restrict__ out) {
    int tid = threadIdx.x;
    __shared__ float r[4];
    float v = g_logz[tid] - g_score[tid];
    #pragma unroll
    for (int o = 16; o; o >>= 1) v += __shfl_down_sync(0xffffffffu, v, o);
    if ((tid & 31) == 0) r[tid >> 5] = v;
    __syncthreads();
    if (tid == 0) out[0] = r[0] + r[1] + r[2] + r[3];
}

// ---------------------------------------------------------------------------
// metadata order: x(int), tags(int), mask(f32, unused), embed(f32), W(f32),
//                 b(f32), trans(f32)  -> out: scalar f32
// ---------------------------------------------------------------------------
extern "C" void kernel_launch(void* const* d_in, const int* in_sizes, int n_in,
                              void* d_out, int out_size) {
    const int*   x     = (const int*)d_in[0];
    const int*   tags  = (const int*)d_in[1];
    const float* embed = (const float*)d_in[3];
    const float* W     = (const float*)d_in[4];
    const float* bias  = (const float*)d_in[5];
    const float* trans = (const float*)d_in[6];
    float* out = (float*)d_out;

    proj_kernel<<<(V_ + 63) / 64, 256>>>(embed, W, bias);
    crf_kernel<<<B_, 128>>>(x, tags, trans);
    reduce_kernel<<<1, 128>>>(out);
}